// round 10
// baseline (speedup 1.0000x reference)
#include <cuda_runtime.h>

// Problem constants (fixed by the reference setup_inputs)
#define NROWS   65536
#define DCOLS   1024
#define WARPS_PER_BLOCK 8
#define GRID    592                      // 148 SMs x 4 resident CTAs: ONE wave
#define TOTAL_WARPS (GRID * WARPS_PER_BLOCK)   // 4736 warps, 13-14 rows each

#define RAD2DEG 57.29577951308232

// Per-block partials (small now: one triple per resident CTA).
__device__ __align__(16) float g_p0[GRID];   // sum of dot^2
__device__ __align__(16) float g_p1[GRID];   // sum of x^2
__device__ __align__(16) float g_p2[GRID];   // sum of y^2
__device__ unsigned int g_count = 0;         // arrival counter; reset by last CTA

__global__ __launch_bounds__(256, 4)
void ang_dif_persistent_kernel(const float* __restrict__ x,
                               const float* __restrict__ y,
                               float* __restrict__ out) {
    const int warp  = threadIdx.x >> 5;
    const int lane  = threadIdx.x & 31;
    const int gwarp = blockIdx.x * WARPS_PER_BLOCK + warp;

    float sdot2 = 0.f;   // identical across lanes (dot is fully xor-reduced)
    float sx = 0.f, sy = 0.f;   // lane-local, reduced once at the end

    // Grid-stride over rows: consecutive warps stream consecutive rows.
    for (int row = gwarp; row < NROWS; row += TOTAL_WARPS) {
        const float4* __restrict__ xr =
            reinterpret_cast<const float4*>(x + (size_t)row * DCOLS);
        const float4* __restrict__ yr =
            reinterpret_cast<const float4*>(y + (size_t)row * DCOLS);

        float dot = 0.f;
        // 1024 floats / row = 256 float4; 32 lanes -> 8 iters, fully coalesced.
        // 16 independent LDG.128 per thread per row (measured-good loop body).
        #pragma unroll
        for (int i = 0; i < 8; ++i) {
            float4 a = xr[lane + i * 32];
            float4 b = yr[lane + i * 32];
            dot = fmaf(a.x, b.x, dot); dot = fmaf(a.y, b.y, dot);
            dot = fmaf(a.z, b.z, dot); dot = fmaf(a.w, b.w, dot);
            sx  = fmaf(a.x, a.x, sx);  sx  = fmaf(a.y, a.y, sx);
            sx  = fmaf(a.z, a.z, sx);  sx  = fmaf(a.w, a.w, sx);
            sy  = fmaf(b.x, b.x, sy);  sy  = fmaf(b.y, b.y, sy);
            sy  = fmaf(b.z, b.z, sy);  sy  = fmaf(b.w, b.w, sy);
        }
        // Per-row warp reduce for dot only; xor pattern leaves the same
        // value in every lane, so dot^2 accumulates without a final reduce.
        #pragma unroll
        for (int o = 16; o > 0; o >>= 1)
            dot += __shfl_xor_sync(0xFFFFFFFFu, dot, o);
        sdot2 = fmaf(dot, dot, sdot2);
    }

    // One warp reduce for the norm sums (deterministic order).
    #pragma unroll
    for (int o = 16; o > 0; o >>= 1) {
        sx += __shfl_xor_sync(0xFFFFFFFFu, sx, o);
        sy += __shfl_xor_sync(0xFFFFFFFFu, sy, o);
    }

    __shared__ float s[WARPS_PER_BLOCK][3];
    if (lane == 0) {
        s[warp][0] = sdot2;
        s[warp][1] = sx;
        s[warp][2] = sy;
    }
    __syncthreads();

    if (threadIdx.x < 3) {
        float acc = 0.f;
        #pragma unroll
        for (int w = 0; w < WARPS_PER_BLOCK; ++w) acc += s[w][threadIdx.x];
        if (threadIdx.x == 0)      g_p0[blockIdx.x] = acc;
        else if (threadIdx.x == 1) g_p1[blockIdx.x] = acc;
        else                       g_p2[blockIdx.x] = acc;
    }

    // ── last-CTA finalization (once per resident CTA: 592 fences total) ──
    __shared__ int is_last;
    __threadfence();               // partials visible before signaling
    __syncthreads();
    if (threadIdx.x == 0) {
        unsigned int c = atomicAdd(&g_count, 1u);
        is_last = (c == (unsigned int)(GRID - 1)) ? 1 : 0;
    }
    __syncthreads();
    if (!is_last) return;

    __threadfence();               // acquire side: order partial reads after count

    // Reduce 592 x 3 floats (7 KB, L2-resident). Fixed order -> deterministic.
    float a0 = 0.f, a1 = 0.f, a2 = 0.f;
    for (int i = threadIdx.x; i < GRID; i += 256) {
        a0 += g_p0[i];
        a1 += g_p1[i];
        a2 += g_p2[i];
    }
    #pragma unroll
    for (int o = 16; o > 0; o >>= 1) {
        a0 += __shfl_xor_sync(0xFFFFFFFFu, a0, o);
        a1 += __shfl_xor_sync(0xFFFFFFFFu, a1, o);
        a2 += __shfl_xor_sync(0xFFFFFFFFu, a2, o);
    }

    __shared__ float f0[WARPS_PER_BLOCK], f1[WARPS_PER_BLOCK], f2[WARPS_PER_BLOCK];
    if (lane == 0) { f0[warp] = a0; f1[warp] = a1; f2[warp] = a2; }
    __syncthreads();

    if (threadIdx.x == 0) {
        double sum_dot2 = 0.0, sxx = 0.0, syy = 0.0;
        #pragma unroll
        for (int w = 0; w < WARPS_PER_BLOCK; ++w) {
            sum_dot2 += (double)f0[w];
            sxx      += (double)f1[w];
            syy      += (double)f2[w];
        }
        // mean((dot / (||x||*||y||) * RAD2DEG)^2)
        //   = RAD2DEG^2 * sum(dot^2) / (N * Sx * Sy)
        double r = (RAD2DEG * RAD2DEG) * sum_dot2 / (sxx * syy * (double)NROWS);
        out[0] = (float)r;
        g_count = 0;               // rearm for next graph replay
    }
}

extern "C" void kernel_launch(void* const* d_in, const int* in_sizes, int n_in,
                              void* d_out, int out_size) {
    const float* x = (const float*)d_in[0];
    const float* y = (const float*)d_in[1];
    float* out = (float*)d_out;

    ang_dif_persistent_kernel<<<GRID, 256>>>(x, y, out);
}

// round 11
// speedup vs baseline: 1.1055x; 1.1055x over previous
#include <cuda_runtime.h>

// Problem constants (fixed by the reference setup_inputs)
#define NROWS   65536
#define DCOLS   1024
#define WARPS_PER_BLOCK 8
#define NBLOCKS (NROWS / WARPS_PER_BLOCK)   // 8192 blocks, 1 row per warp

#define RAD2DEG 57.29577951308232

// Deterministic per-block partials: [0..NBLOCKS) = sum(dot^2),
// [NBLOCKS..2N) = sum(x^2), [2N..3N) = sum(y^2). Fully overwritten every call.
// 16B-aligned so the finalize kernel can read it as float4.
__device__ __align__(16) float g_partials[NBLOCKS * 3];

// ── Streaming kernel: EXACT copy of the R6 kernel measured at 6.87 TB/s ──
// (one row per warp, 16 independent LDG.128 in flight per thread, no fence,
//  no atomic, no per-row shuffle chain carried across rows). Do not disturb.
__global__ __launch_bounds__(256, 4)
void rowdot_kernel(const float* __restrict__ x, const float* __restrict__ y) {
    const int warp = threadIdx.x >> 5;
    const int lane = threadIdx.x & 31;
    const int row  = blockIdx.x * WARPS_PER_BLOCK + warp;

    const float4* __restrict__ xr =
        reinterpret_cast<const float4*>(x + (size_t)row * DCOLS);
    const float4* __restrict__ yr =
        reinterpret_cast<const float4*>(y + (size_t)row * DCOLS);

    float dot = 0.f, sx = 0.f, sy = 0.f;
    // 1024 floats / row = 256 float4; 32 lanes -> 8 iters, fully coalesced.
    #pragma unroll
    for (int i = 0; i < 8; ++i) {
        float4 a = xr[lane + i * 32];
        float4 b = yr[lane + i * 32];
        dot = fmaf(a.x, b.x, dot); dot = fmaf(a.y, b.y, dot);
        dot = fmaf(a.z, b.z, dot); dot = fmaf(a.w, b.w, dot);
        sx  = fmaf(a.x, a.x, sx);  sx  = fmaf(a.y, a.y, sx);
        sx  = fmaf(a.z, a.z, sx);  sx  = fmaf(a.w, a.w, sx);
        sy  = fmaf(b.x, b.x, sy);  sy  = fmaf(b.y, b.y, sy);
        sy  = fmaf(b.z, b.z, sy);  sy  = fmaf(b.w, b.w, sy);
    }

    // Warp tree reduce (deterministic order)
    #pragma unroll
    for (int o = 16; o > 0; o >>= 1) {
        dot += __shfl_xor_sync(0xFFFFFFFFu, dot, o);
        sx  += __shfl_xor_sync(0xFFFFFFFFu, sx,  o);
        sy  += __shfl_xor_sync(0xFFFFFFFFu, sy,  o);
    }

    __shared__ float s[WARPS_PER_BLOCK][3];
    if (lane == 0) {
        s[warp][0] = dot * dot;   // per-row contribution is dot^2
        s[warp][1] = sx;
        s[warp][2] = sy;
    }
    __syncthreads();

    if (threadIdx.x < 3) {
        float acc = 0.f;
        #pragma unroll
        for (int w = 0; w < WARPS_PER_BLOCK; ++w) acc += s[w][threadIdx.x];
        g_partials[(size_t)threadIdx.x * NBLOCKS + blockIdx.x] = acc;
    }
}

// ── Finalize: vectorized. 96 KB of L2-hot partials via 6 independent
//    LDG.128 per thread (front-batched, max MLP), instead of 24 scalar LDGs.
__global__ __launch_bounds__(1024)
void finalize_kernel(float* __restrict__ out) {
    const int tid  = threadIdx.x;
    const int warp = tid >> 5;
    const int lane = tid & 31;

    // Each section is NBLOCKS floats = 2048 float4. 1024 threads -> 2 each.
    const float4* __restrict__ p4 = reinterpret_cast<const float4*>(g_partials);

    float4 v00 = p4[tid];                 // dot^2 section
    float4 v01 = p4[tid + 1024];
    float4 v10 = p4[2048 + tid];          // sum x^2 section
    float4 v11 = p4[2048 + tid + 1024];
    float4 v20 = p4[4096 + tid];          // sum y^2 section
    float4 v21 = p4[4096 + tid + 1024];

    float a0 = ((v00.x + v00.y) + (v00.z + v00.w))
             + ((v01.x + v01.y) + (v01.z + v01.w));
    float a1 = ((v10.x + v10.y) + (v10.z + v10.w))
             + ((v11.x + v11.y) + (v11.z + v11.w));
    float a2 = ((v20.x + v20.y) + (v20.z + v20.w))
             + ((v21.x + v21.y) + (v21.z + v21.w));

    #pragma unroll
    for (int o = 16; o > 0; o >>= 1) {
        a0 += __shfl_xor_sync(0xFFFFFFFFu, a0, o);
        a1 += __shfl_xor_sync(0xFFFFFFFFu, a1, o);
        a2 += __shfl_xor_sync(0xFFFFFFFFu, a2, o);
    }

    __shared__ float s0[32], s1[32], s2[32];
    if (lane == 0) { s0[warp] = a0; s1[warp] = a1; s2[warp] = a2; }
    __syncthreads();

    if (warp == 0) {
        float v0 = s0[lane], v1 = s1[lane], v2 = s2[lane];
        #pragma unroll
        for (int o = 16; o > 0; o >>= 1) {
            v0 += __shfl_xor_sync(0xFFFFFFFFu, v0, o);
            v1 += __shfl_xor_sync(0xFFFFFFFFu, v1, o);
            v2 += __shfl_xor_sync(0xFFFFFFFFu, v2, o);
        }
        if (lane == 0) {
            // mean((dot / (||x||*||y||) * RAD2DEG)^2)
            //   = RAD2DEG^2 * sum(dot^2) / (N * Sx * Sy)
            double sum_dot2 = (double)v0;
            double sxx = (double)v1;
            double syy = (double)v2;
            double r = (RAD2DEG * RAD2DEG) * sum_dot2 / (sxx * syy * (double)NROWS);
            out[0] = (float)r;
        }
    }
}

extern "C" void kernel_launch(void* const* d_in, const int* in_sizes, int n_in,
                              void* d_out, int out_size) {
    const float* x = (const float*)d_in[0];
    const float* y = (const float*)d_in[1];
    float* out = (float*)d_out;

    rowdot_kernel<<<NBLOCKS, 256>>>(x, y);
    finalize_kernel<<<1, 1024>>>(out);
}